// round 17
// baseline (speedup 1.0000x reference)
#include <cuda_runtime.h>
#include <cstdint>

#define SEQ     512
#define BATCH   64
#define HID     1024
#define TWOH    2048
#define NLAYER  2
#define NDEPTH  4

#define GRID    128      // CTAs; each owns 8 h-cols + paired 8 g-cols
#define NTH     512
#define KC      64       // K-chunk
#define NCH     (HID / KC)   // 16
#define SPAD    65       // s-tile row stride (odd -> conflict-free)
#define CPC     8        // h-columns per CTA
#define NKS     8        // split-K slices
#define RPAD    17       // reduction row stride
#define RSL     (64 * RPAD)   // 1088 floats per k-slice

// shared pool layout (floats)
#define S_OFF   0                 // s-tiles: 2 * 64 * SPAD = 8320
#define W_OFF   (2 * 64 * SPAD)
#define POOLSZ  (W_OFF + 2 * KC * 16)   // 10368 floats = 41472 B (>= 8*RSL=8704)

#define FMA2(acc, a, w) \
    asm("fma.rn.f32x2 %0, %1, %2, %0;" : "+l"(acc) : "l"(a), "l"(w))
#define BCAST2(d, f) \
    do { unsigned _u = __float_as_uint(f); \
         asm("mov.b64 %0, {%1, %1};" : "=l"(d) : "r"(_u)); } while (0)
#define UNPK2(lo, hi, v) \
    do { unsigned _l, _h; \
         asm("mov.b64 {%0, %1}, %2;" : "=r"(_l), "=r"(_h) : "l"(v)); \
         lo = __uint_as_float(_l); hi = __uint_as_float(_h); } while (0)

// ---------------- device scratch (no cudaMalloc allowed) ----------------
__device__ float    g_S[NLAYER][2][BATCH * HID];   // double-buffered state
__device__ unsigned g_bar_count;
__device__ unsigned g_bar_gen;

// ---------------- software grid barrier (128 co-resident CTAs) ----------
__device__ __forceinline__ void grid_barrier() {
    __syncthreads();
    if (threadIdx.x == 0) {
        __threadfence();                         // publish this CTA's stores
        volatile unsigned* genp = &g_bar_gen;
        unsigned gen = *genp;
        if (atomicAdd(&g_bar_count, 1u) == GRID - 1u) {
            atomicExch(&g_bar_count, 0u);        // reset BEFORE release
            __threadfence();
            atomicExch(&g_bar_gen, gen + 1u);    // release
        } else {
            while (*genp == gen) {}
            __threadfence();                     // acquire
        }
    }
    __syncthreads();
}

// ---------------- one GEMM pass: acc += A[64,1024] @ W[:, 16 CTA cols] ---
// Thread (rg=tid&15, cg=(tid>>4)&3, ks=tid>>6) accumulates rows {rg+16i}
// x cols [cg*4, cg*4+4) over k = kk*8 + ks (interleaved 8-way split-K).
// acc[i*2+p] packs cols (cg*4+2p, cg*4+2p+1) for row rg+16i  (f32x2).
__device__ __forceinline__ void gemm_acc(
    const float* __restrict__ A,       // [64,1024]; bypass L1 (remote-written)
    const float* __restrict__ W,       // [1024,2048]; immutable -> L1 ok
    float* __restrict__ pool,
    int wcol, int tid, unsigned long long* acc)
{
    const int rg  = tid & 15;
    const int cg4 = ((tid >> 4) & 3) * 4;
    const int ks  = tid >> 6;

    const int lrow = tid >> 3;          // A row this thread stages
    const int lq   = (tid & 7) * 8;     // 8-float segment of 64-float chunk
    const int wk   = tid >> 3;          // W k-row this thread stages
    const int wn   = (tid & 7) * 2;     // staging col pair

    float* s_sm = pool + S_OFF;
    float* w_sm = pool + W_OFF;

    // prologue: stage chunk 0
    float4 ra0 = __ldcg((const float4*)(A + lrow * HID + lq));
    float4 ra1 = __ldcg((const float4*)(A + lrow * HID + lq + 4));
    float2 rw  = *(const float2*)(W + (size_t)wk * TWOH + wcol);
    {
        float* sd = s_sm + lrow * SPAD + lq;
        sd[0]=ra0.x; sd[1]=ra0.y; sd[2]=ra0.z; sd[3]=ra0.w;
        sd[4]=ra1.x; sd[5]=ra1.y; sd[6]=ra1.z; sd[7]=ra1.w;
        float* wd = w_sm + wk * 16 + wn;
        wd[0]=rw.x; wd[1]=rw.y;
    }
    __syncthreads();

#pragma unroll 1
    for (int ch = 0; ch < NCH; ch++) {
        // prefetch next chunk into registers (overlaps compute)
        if (ch + 1 < NCH) {
            const int k0 = (ch + 1) * KC;
            ra0 = __ldcg((const float4*)(A + lrow * HID + k0 + lq));
            ra1 = __ldcg((const float4*)(A + lrow * HID + k0 + lq + 4));
            rw  = *(const float2*)(W + (size_t)(k0 + wk) * TWOH + wcol);
        }
        // compute current chunk: 8 interleaved k's for this slice
        const float* sb = s_sm + (ch & 1) * (64 * SPAD);
        const float* wb = w_sm + (ch & 1) * (KC * 16);
        const float* ap0 = sb + rg * SPAD + ks;
        const float* ap1 = ap0 + 16 * SPAD;
        const float* ap2 = ap0 + 32 * SPAD;
        const float* ap3 = ap0 + 48 * SPAD;
        unsigned wadr = (unsigned)__cvta_generic_to_shared(wb + ks * 16 + cg4);
#pragma unroll
        for (int kk = 0; kk < KC / NKS; kk++) {
            unsigned long long wlo, whi;
            asm("ld.shared.v2.b64 {%0, %1}, [%2];"
                : "=l"(wlo), "=l"(whi) : "r"(wadr + kk * (NKS * 16 * 4)));
            float a0 = ap0[kk * NKS];
            float a1 = ap1[kk * NKS];
            float a2 = ap2[kk * NKS];
            float a3 = ap3[kk * NKS];
            unsigned long long A0, A1, A2, A3;
            BCAST2(A0, a0); BCAST2(A1, a1); BCAST2(A2, a2); BCAST2(A3, a3);
            FMA2(acc[0], A0, wlo); FMA2(acc[1], A0, whi);
            FMA2(acc[2], A1, wlo); FMA2(acc[3], A1, whi);
            FMA2(acc[4], A2, wlo); FMA2(acc[5], A2, whi);
            FMA2(acc[6], A3, wlo); FMA2(acc[7], A3, whi);
        }
        // stage next chunk into the other buffer
        if (ch + 1 < NCH) {
            const int nb = (ch + 1) & 1;
            float* sd = s_sm + nb * (64 * SPAD) + lrow * SPAD + lq;
            sd[0]=ra0.x; sd[1]=ra0.y; sd[2]=ra0.z; sd[3]=ra0.w;
            sd[4]=ra1.x; sd[5]=ra1.y; sd[6]=ra1.z; sd[7]=ra1.w;
            float* wd = w_sm + nb * (KC * 16) + wk * 16 + wn;
            wd[0]=rw.x; wd[1]=rw.y;
        }
        __syncthreads();
    }
}

// ---------------- persistent RHN kernel ---------------------------------
__global__ void __launch_bounds__(NTH, 1) rhn_kernel(
    const float* __restrict__ x,     // [512, 64, 1024]
    const float* __restrict__ st0,   // [2, 64, 1024]
    const float* __restrict__ w_in,  // [2, 1024, 2048]
    const float* __restrict__ w_h,   // [2, 4, 1024, 2048]
    const float* __restrict__ b_h,   // [2, 4, 2048]
    float* __restrict__ out)         // [512,64,1024] ++ [2,64,1024]
{
    __shared__ __align__(16) float pool[POOLSZ];

    const int c   = blockIdx.x;
    const int tid = threadIdx.x;
    const int rg  = tid & 15;
    const int cg4 = ((tid >> 4) & 3) * 4;
    const int ks  = tid >> 6;

    // staging weight column
    const int wn   = (tid & 7) * 2;
    const int wcol = (wn < 8) ? (c * CPC + wn) : (HID + c * CPC + (wn - 8));

    // gating identity: thread handles (b, j), j in [0,8)
    const int gb = tid >> 3;
    const int gj = tid & 7;
    const int gcol = c * CPC + gj;

    // init state into parity 0
    for (int i = tid; i < NLAYER * BATCH * CPC; i += NTH) {
        int l = i >> 9;
        int b = (i >> 3) & 63;
        int j = i & 7;
        int col = c * CPC + j;
        g_S[l][0][b * HID + col] = st0[(size_t)l * BATCH * HID + b * HID + col];
    }
    grid_barrier();

#pragma unroll 1
    for (int t = 0; t < SEQ; t++) {
        const float* xt = x + (size_t)t * BATCH * HID;
#pragma unroll 1
        for (int l = 0; l < NLAYER; l++) {
            const float* inp = (l == 0) ? xt : g_S[0][0];
#pragma unroll 1
            for (int d = 0; d < NDEPTH; d++) {
                const float* scur = g_S[l][d & 1];
                float*       snxt = g_S[l][(d + 1) & 1];
                const float* W = w_h + (size_t)(l * NDEPTH + d) * HID * TWOH;

                unsigned long long acc[8] = {0ull,0ull,0ull,0ull,0ull,0ull,0ull,0ull};
                gemm_acc(scur, W, pool, wcol, tid, acc);
                if (d == 0) {
                    const float* Wi = w_in + (size_t)l * HID * TWOH;
                    gemm_acc(inp, Wi, pool, wcol, tid, acc);
                }

                // split-K partials into smem (aliases tiles; GEMM ended w/ sync)
                float* red = pool;
#pragma unroll
                for (int i = 0; i < 4; i++) {
                    float l0, h0, l1, h1;
                    UNPK2(l0, h0, acc[i * 2]);
                    UNPK2(l1, h1, acc[i * 2 + 1]);
                    float* p = red + ks * RSL + (rg + 16 * i) * RPAD + cg4;
                    p[0] = l0; p[1] = h0; p[2] = l1; p[3] = h1;
                }
                __syncthreads();

                // gating: thread (gb, gj) sums 8 partials for h and g, + bias
                {
                    const float* bb = b_h + (size_t)(l * NDEPTH + d) * TWOH;
                    float hh = bb[gcol];
                    float hg = bb[HID + gcol];
                    int base = gb * RPAD + gj;
#pragma unroll
                    for (int s = 0; s < NKS; s++) {
                        hh += red[s * RSL + base];
                        hg += red[s * RSL + base + 8];
                    }
                    float hv = tanhf(hh);
                    float gv = 1.0f / (1.0f + expf(-hg));
                    float sold = __ldcg(scur + gb * HID + gcol);
                    float sn = fmaf(gv, hv - sold, sold);   // h*g + s*(1-g)
                    snxt[gb * HID + gcol] = sn;
                    if (l == NLAYER - 1 && d == NDEPTH - 1)
                        out[(size_t)t * BATCH * HID + gb * HID + gcol] = sn;
                }
                __syncthreads();          // red reads done before pool reuse
                grid_barrier();
            }
        }
    }

    // final_s (both layers end each timestep at parity 0)
    const size_t fin = (size_t)SEQ * BATCH * HID;
    for (int i = tid; i < NLAYER * BATCH * CPC; i += NTH) {
        int l = i >> 9;
        int b = (i >> 3) & 63;
        int j = i & 7;
        int col = c * CPC + j;
        out[fin + (size_t)l * BATCH * HID + b * HID + col] = g_S[l][0][b * HID + col];
    }
}

// ---------------- launch -------------------------------------------------
extern "C" void kernel_launch(void* const* d_in, const int* in_sizes, int n_in,
                              void* d_out, int out_size) {
    const float* x   = (const float*)d_in[0];   // x      [512,64,1024]
    const float* st  = (const float*)d_in[1];   // state  [2,64,1024]
    const float* wi  = (const float*)d_in[2];   // w_in   [2,1024,2048]
    const float* wh  = (const float*)d_in[3];   // w_h    [2,4,1024,2048]
    const float* bh  = (const float*)d_in[4];   // b_h    [2,4,2048]
    (void)in_sizes; (void)n_in; (void)out_size;
    rhn_kernel<<<GRID, NTH>>>(x, st, wi, wh, bh, (float*)d_out);
}